// round 14
// baseline (speedup 1.0000x reference)
#include <cuda_runtime.h>
#include <cuda_fp16.h>
#include <math.h>
#include <stdint.h>

// Problem dims (fixed per reference)
#define NROWS 8192
#define NFEAT 512
#define NHID  256
#define NCAT  768   // NHID + NFEAT

// ---------------------------------------------------------------------------
// Scratch (static device globals)
// ---------------------------------------------------------------------------
__device__ __half g_xwT [NHID * NROWS];
__device__ __half g_h1  [NROWS * NHID];
__device__ __half g_h1wT[NHID * NROWS];
__device__ __half g_cat [NROWS * NCAT];
__device__ __half g_o4  [NROWS * NCAT];
__device__ __half g_o5  [NROWS * NCAT];
__device__ __half g_w1T [NHID * NFEAT];
__device__ __half g_w2T [NHID * NHID];
__device__ __half g_l1T [NCAT * NCAT];
__device__ __half g_l2T [NCAT * NCAT];
__device__ __half g_l3T [NFEAT * NCAT];

// ---------------------------------------------------------------------------
// Helpers (baseline PTX only)
// ---------------------------------------------------------------------------
__device__ __forceinline__ uint32_t smem_u32(const void* p) {
    uint32_t a;
    asm("{ .reg .u64 t; cvta.to.shared.u64 t, %1; cvt.u32.u64 %0, t; }"
        : "=r"(a) : "l"(p));
    return a;
}
__device__ __forceinline__ void cpasync16(uint32_t dst, const void* src) {
    asm volatile("cp.async.cg.shared.global [%0], [%1], 16;" :: "r"(dst), "l"(src));
}
__device__ __forceinline__ void cp_commit() {
    asm volatile("cp.async.commit_group;" ::: "memory");
}
__device__ __forceinline__ void cp_wait1() {
    asm volatile("cp.async.wait_group 1;" ::: "memory");
}
__device__ __forceinline__ void cp_wait2() {
    asm volatile("cp.async.wait_group 2;" ::: "memory");
}
__device__ __forceinline__ void cp_wait0() {
    asm volatile("cp.async.wait_group 0;" ::: "memory");
}
__device__ __forceinline__ void ldsm_x4(uint32_t* r, uint32_t addr) {
    asm volatile("ldmatrix.sync.aligned.m8n8.x4.shared.b16 {%0,%1,%2,%3}, [%4];"
                 : "=r"(r[0]), "=r"(r[1]), "=r"(r[2]), "=r"(r[3]) : "r"(addr));
}
__device__ __forceinline__ void mma_f16(float* c, const uint32_t* a, const uint32_t* b) {
    asm volatile(
        "mma.sync.aligned.m16n8k16.row.col.f32.f16.f16.f32 "
        "{%0,%1,%2,%3}, {%4,%5,%6,%7}, {%8,%9}, {%0,%1,%2,%3};"
        : "+f"(c[0]), "+f"(c[1]), "+f"(c[2]), "+f"(c[3])
        : "r"(a[0]), "r"(a[1]), "r"(a[2]), "r"(a[3]), "r"(b[0]), "r"(b[1]));
}
// fp16-accumulator variant: D,C are 2x b32 (4 halfs).
__device__ __forceinline__ void mma_f16h(uint32_t* c, const uint32_t* a, const uint32_t* b) {
    asm volatile(
        "mma.sync.aligned.m16n8k16.row.col.f16.f16.f16.f16 "
        "{%0,%1}, {%2,%3,%4,%5}, {%6,%7}, {%0,%1};"
        : "+r"(c[0]), "+r"(c[1])
        : "r"(a[0]), "r"(a[1]), "r"(a[2]), "r"(a[3]), "r"(b[0]), "r"(b[1]));
}
__device__ __forceinline__ uint32_t h2u(__half2 h) { return *(uint32_t*)&h; }

// ---------------------------------------------------------------------------
// Tiling: BM=64, BN=128, BK=64, 256 threads (8 warps 2x4), warp tile 32x32.
// fp16 tile row = 64 halfs (128B) + 16B pad = 144B -> conflict-free ldmatrix.
// ---------------------------------------------------------------------------
#define BM 64
#define BN 128
#define BK 64
#define ROWB 144
#define A_TILE (BM * ROWB)          // 9216
#define B_TILE (BN * ROWB)          // 18432
#define P_STAGE (A_TILE + B_TILE)   // 27648
#define DYN_P (3 * P_STAGE)         // 82944  -> occupancy 2
#define HC_B_OFF (2 * A_TILE)       // 18432
#define DYN_HC (HC_B_OFF + 4 * B_TILE)  // 92160 -> occupancy 2

// A half tile: 64 rows x 8 chunks = 512, 2/thread
__device__ __forceinline__ void load_a_tile(uint32_t base, int tid,
                                            const __half* rowp, int K, int k0) {
    #pragma unroll
    for (int i = 0; i < 2; i++) {
        const int c = tid + i * 256;
        const int row = c >> 3, q = c & 7;
        cpasync16(base + row * ROWB + q * 16, rowp + (size_t)row * K + k0 + q * 8);
    }
}
// B half tile: 128 rows x 8 chunks = 1024, 4/thread
__device__ __forceinline__ void load_b_tile(uint32_t base, int tid,
                                            const __half* rowp, int K, int k0) {
    #pragma unroll
    for (int i = 0; i < 4; i++) {
        const int c = tid + i * 256;
        const int row = c >> 3, q = c & 7;
        cpasync16(base + row * ROWB + q * 16, rowp + (size_t)row * K + k0 + q * 8);
    }
}

// fp32 A: 16 consecutive floats per thread (4x LDG.128)
__device__ __forceinline__ void ldg16(float* ar, const float* p) {
    float4 v0 = ((const float4*)p)[0];
    float4 v1 = ((const float4*)p)[1];
    float4 v2 = ((const float4*)p)[2];
    float4 v3 = ((const float4*)p)[3];
    ar[0]  = v0.x; ar[1]  = v0.y; ar[2]  = v0.z; ar[3]  = v0.w;
    ar[4]  = v1.x; ar[5]  = v1.y; ar[6]  = v1.z; ar[7]  = v1.w;
    ar[8]  = v2.x; ar[9]  = v2.y; ar[10] = v2.z; ar[11] = v2.w;
    ar[12] = v3.x; ar[13] = v3.y; ar[14] = v3.z; ar[15] = v3.w;
}
// convert 16 floats * alpha -> 16 halfs -> 2x STS.128
__device__ __forceinline__ void cvt_sts(const float* ar, uint32_t dst, float alpha) {
    uint32_t o[8];
    #pragma unroll
    for (int i = 0; i < 8; i++)
        o[i] = h2u(__floats2half2_rn(ar[2 * i] * alpha, ar[2 * i + 1] * alpha));
    asm volatile("st.shared.v4.b32 [%0], {%1,%2,%3,%4};"
                 :: "r"(dst), "r"(o[0]), "r"(o[1]), "r"(o[2]), "r"(o[3]));
    asm volatile("st.shared.v4.b32 [%0], {%1,%2,%3,%4};"
                 :: "r"(dst + 16), "r"(o[4]), "r"(o[5]), "r"(o[6]), "r"(o[7]));
}

// ---- fragment load for one k-step ----
__device__ __forceinline__ void ld_frags(uint32_t aBase, uint32_t bBase4, int ks,
                                         uint32_t af[2][4], uint32_t bf[4][2]) {
    ldsm_x4(af[0], aBase + ks * 32);
    ldsm_x4(af[1], aBase + 16 * ROWB + ks * 32);
    uint32_t q[4];
    ldsm_x4(q, bBase4 + ks * 32);
    bf[0][0] = q[0]; bf[0][1] = q[1]; bf[1][0] = q[2]; bf[1][1] = q[3];
    ldsm_x4(q, bBase4 + 16 * ROWB + ks * 32);
    bf[2][0] = q[0]; bf[2][1] = q[1]; bf[3][0] = q[2]; bf[3][1] = q[3];
}

// ---- mainloop body (fp32 acc) ----
__device__ __forceinline__ void mma_tile(float acc[2][4][4],
                                         uint32_t aBase, uint32_t bBase4) {
    uint32_t af[2][2][4], bf[2][4][2];
    ld_frags(aBase, bBase4, 0, af[0], bf[0]);
    #pragma unroll
    for (int ks = 0; ks < 4; ks++) {
        const int cur = ks & 1;
        if (ks < 3)
            ld_frags(aBase, bBase4, ks + 1, af[cur ^ 1], bf[cur ^ 1]);
        #pragma unroll
        for (int mt = 0; mt < 2; mt++)
            #pragma unroll
            for (int nt = 0; nt < 4; nt++)
                mma_f16(acc[mt][nt], af[cur][mt], bf[cur][nt]);
    }
}
// ---- mainloop body (fp16 acc) ----
__device__ __forceinline__ void mma_tile_h(uint32_t acc[2][4][2],
                                           uint32_t aBase, uint32_t bBase4) {
    uint32_t af[2][2][4], bf[2][4][2];
    ld_frags(aBase, bBase4, 0, af[0], bf[0]);
    #pragma unroll
    for (int ks = 0; ks < 4; ks++) {
        const int cur = ks & 1;
        if (ks < 3)
            ld_frags(aBase, bBase4, ks + 1, af[cur ^ 1], bf[cur ^ 1]);
        #pragma unroll
        for (int mt = 0; mt < 2; mt++)
            #pragma unroll
            for (int nt = 0; nt < 4; nt++)
                mma_f16h(acc[mt][nt], af[cur][mt], bf[cur][nt]);
    }
}

// ---- epilogue (fp32 acc): normal or transposed ----
template <bool RELU, bool BIAS, bool HALF_OUT, bool TRANS>
__device__ __forceinline__ void epilogue(float acc[2][4][4], float scale,
                                         const float* bias, void* C, int ldc,
                                         int m0, int n0, int wm, int wn,
                                         int lane, int wid, uint8_t* scratch) {
    if (!TRANS) {
        const int rbase = m0 + wm * 32 + (lane >> 2);
        const int cbase = n0 + wn * 32 + 2 * (lane & 3);
        #pragma unroll
        for (int mt = 0; mt < 2; mt++) {
            #pragma unroll
            for (int nt = 0; nt < 4; nt++) {
                const int col = cbase + nt * 8;
                float b0 = 0.0f, b1 = 0.0f;
                if (BIAS) { b0 = bias[col]; b1 = bias[col + 1]; }
                float v0 = acc[mt][nt][0] * scale + b0;
                float v1 = acc[mt][nt][1] * scale + b1;
                float v2 = acc[mt][nt][2] * scale + b0;
                float v3 = acc[mt][nt][3] * scale + b1;
                if (RELU) {
                    v0 = fmaxf(v0, 0.0f); v1 = fmaxf(v1, 0.0f);
                    v2 = fmaxf(v2, 0.0f); v3 = fmaxf(v3, 0.0f);
                }
                const int row = rbase + mt * 16;
                if (HALF_OUT) {
                    __half* Ch = (__half*)C;
                    *(__half2*)(Ch + (size_t)row * ldc + col)       = __floats2half2_rn(v0, v1);
                    *(__half2*)(Ch + (size_t)(row + 8) * ldc + col) = __floats2half2_rn(v2, v3);
                } else {
                    float* Cf = (float*)C;
                    *(float2*)(Cf + (size_t)row * ldc + col)       = make_float2(v0, v1);
                    *(float2*)(Cf + (size_t)(row + 8) * ldc + col) = make_float2(v2, v3);
                }
            }
        }
    } else {
        __half* sw = (__half*)scratch + (size_t)wid * (32 * 40);
        #pragma unroll
        for (int mt = 0; mt < 2; mt++) {
            #pragma unroll
            for (int nt = 0; nt < 4; nt++) {
                const int r = (lane >> 2) + mt * 16;
                const int c = 2 * (lane & 3) + nt * 8;
                sw[(size_t)c * 40 + r]           = __float2half(acc[mt][nt][0] * scale);
                sw[(size_t)(c + 1) * 40 + r]     = __float2half(acc[mt][nt][1] * scale);
                sw[(size_t)c * 40 + r + 8]       = __float2half(acc[mt][nt][2] * scale);
                sw[(size_t)(c + 1) * 40 + r + 8] = __float2half(acc[mt][nt][3] * scale);
            }
        }
        __syncwarp();
        __half* dst = (__half*)C + (size_t)(n0 + wn * 32 + lane) * ldc + m0 + wm * 32;
        const uint4* srow = (const uint4*)(sw + (size_t)lane * 40);
        uint4* d4 = (uint4*)dst;
        #pragma unroll
        for (int i = 0; i < 4; i++) d4[i] = srow[i];
    }
}

// ---------------------------------------------------------------------------
// Pure fp16 GEMM (fp32 acc): 3-stage pipeline, one sync/iter.  K%64==0, KT>=2.
// ---------------------------------------------------------------------------
template <bool RELU, bool BIAS, bool HALF_OUT, bool TRANS>
__global__ __launch_bounds__(256, 2)
void h_gemm(int K, int ldc,
            const __half* __restrict__ A, const __half* __restrict__ Bt,
            const float* __restrict__ bias, void* __restrict__ C, float scale)
{
    extern __shared__ __align__(16) uint8_t dsraw[];
    const uint32_t smem = smem_u32(dsraw);
    const int tid = threadIdx.x, wid = tid >> 5, lane = tid & 31;
    const int wm = wid >> 2, wn = wid & 3;
    const int m0 = blockIdx.y * BM, n0 = blockIdx.x * BN;
    const int KT = K / BK;

    const __half* Arow = A + (size_t)m0 * K;
    const __half* Brow = Bt + (size_t)n0 * K;

    float acc[2][4][4];
    #pragma unroll
    for (int mt = 0; mt < 2; mt++)
        #pragma unroll
        for (int nt = 0; nt < 4; nt++)
            #pragma unroll
            for (int i = 0; i < 4; i++) acc[mt][nt][i] = 0.0f;

    const uint32_t aOff = (uint32_t)(wm * 32 + (lane & 15)) * ROWB + (lane >> 4) * 16;
    const uint32_t bOff4 = (uint32_t)(wn * 32 + (lane & 7) + ((lane >> 4) & 1) * 8) * ROWB
                         + ((lane >> 3) & 1) * 16;

    #pragma unroll
    for (int tt = 0; tt < 2; tt++) {
        const uint32_t st = smem + (uint32_t)tt * P_STAGE;
        load_a_tile(st, tid, Arow, K, tt * BK);
        load_b_tile(st + A_TILE, tid, Brow, K, tt * BK);
        cp_commit();
    }
    cp_wait1();

    int s = 0;
    for (int t = 0; t < KT; t++) {
        __syncthreads();
        if (t + 2 < KT) {
            const int sw = (s + 2 >= 3) ? s - 1 : s + 2;
            const uint32_t st = smem + (uint32_t)sw * P_STAGE;
            load_a_tile(st, tid, Arow, K, (t + 2) * BK);
            load_b_tile(st + A_TILE, tid, Brow, K, (t + 2) * BK);
        }
        cp_commit();
        const uint32_t st = smem + (uint32_t)s * P_STAGE;
        mma_tile(acc, st + aOff, st + A_TILE + bOff4);
        cp_wait1();
        s = (s + 1 == 3) ? 0 : s + 1;
    }
    cp_wait0();
    __syncthreads();
    epilogue<RELU, BIAS, HALF_OUT, TRANS>(acc, scale, bias, C, ldc,
                                          m0, n0, wm, wn, lane, wid, dsraw);
}

// ---------------------------------------------------------------------------
// fp32-A fused-convert GEMM, fp32 acc (GEMM1).  One sync/iter.  KT>=3.
// ---------------------------------------------------------------------------
template <bool RELU, bool BIAS, bool HALF_OUT, bool TRANS>
__global__ __launch_bounds__(256, 2)
void hc_gemm(int K, int ldc,
             const float* __restrict__ A, const __half* __restrict__ Bt,
             const float* __restrict__ bias, void* __restrict__ C,
             float alpha, float scale)
{
    extern __shared__ __align__(16) uint8_t dsraw[];
    const uint32_t smem = smem_u32(dsraw);
    const int tid = threadIdx.x, wid = tid >> 5, lane = tid & 31;
    const int wm = wid >> 2, wn = wid & 3;
    const int m0 = blockIdx.y * BM, n0 = blockIdx.x * BN;
    const int KT = K / BK;

    const float* Arow = A + (size_t)m0 * K;
    const __half* Brow = Bt + (size_t)n0 * K;

    float acc[2][4][4];
    #pragma unroll
    for (int mt = 0; mt < 2; mt++)
        #pragma unroll
        for (int nt = 0; nt < 4; nt++)
            #pragma unroll
            for (int i = 0; i < 4; i++) acc[mt][nt][i] = 0.0f;

    const uint32_t aOff = (uint32_t)(wm * 32 + (lane & 15)) * ROWB + (lane >> 4) * 16;
    const uint32_t bOff4 = (uint32_t)(wn * 32 + (lane & 7) + ((lane >> 4) & 1) * 8) * ROWB
                         + ((lane >> 3) & 1) * 16;

    const int crow = tid >> 2, cq = tid & 3;
    const float* aptr0 = Arow + (size_t)crow * K + cq * 16;
    const uint32_t cvtDstBase = smem + crow * ROWB + cq * 32;

    float ar[16];
    ldg16(ar, aptr0);
    load_b_tile(smem + HC_B_OFF, tid, Brow, K, 0);             cp_commit();
    load_b_tile(smem + HC_B_OFF + B_TILE, tid, Brow, K, BK);   cp_commit();
    load_b_tile(smem + HC_B_OFF + 2 * B_TILE, tid, Brow, K, 2 * BK); cp_commit();
    cvt_sts(ar, cvtDstBase, alpha);
    if (KT > 1) ldg16(ar, aptr0 + BK);
    cp_wait2();

    for (int t = 0; t < KT; t++) {
        __syncthreads();
        if (t + 1 < KT)
            cvt_sts(ar, cvtDstBase + (uint32_t)((t + 1) & 1) * A_TILE, alpha);
        if (t + 2 < KT)
            ldg16(ar, aptr0 + (size_t)(t + 2) * BK);
        if (t + 3 < KT)
            load_b_tile(smem + HC_B_OFF + (uint32_t)((t + 3) & 3) * B_TILE,
                        tid, Brow, K, (t + 3) * BK);
        cp_commit();
        mma_tile(acc, smem + (uint32_t)(t & 1) * A_TILE + aOff,
                 smem + HC_B_OFF + (uint32_t)(t & 3) * B_TILE + bOff4);
        cp_wait2();
    }
    cp_wait0();
    __syncthreads();
    epilogue<RELU, BIAS, HALF_OUT, TRANS>(acc, scale, bias, C, ldc,
                                          m0, n0, wm, wn, lane, wid, dsraw);
}

// ---------------------------------------------------------------------------
// fp32-A fused-convert GEMM with FP16 ACCUMULATORS (adjacency GEMMs only).
// C_h = (alpha*A_f32) @ Bt_h^T * scale (+bias)(+relu), half out, direct store.
// ---------------------------------------------------------------------------
template <bool RELU>
__global__ __launch_bounds__(256, 2)
void hc_gemm_hacc(int K, int ldc,
                  const float* __restrict__ A, const __half* __restrict__ Bt,
                  const float* __restrict__ bias, __half* __restrict__ C,
                  float alpha, float scale)
{
    extern __shared__ __align__(16) uint8_t dsraw[];
    const uint32_t smem = smem_u32(dsraw);
    const int tid = threadIdx.x, wid = tid >> 5, lane = tid & 31;
    const int wm = wid >> 2, wn = wid & 3;
    const int m0 = blockIdx.y * BM, n0 = blockIdx.x * BN;
    const int KT = K / BK;

    const float* Arow = A + (size_t)m0 * K;
    const __half* Brow = Bt + (size_t)n0 * K;

    uint32_t acc[2][4][2];
    #pragma unroll
    for (int mt = 0; mt < 2; mt++)
        #pragma unroll
        for (int nt = 0; nt < 4; nt++) { acc[mt][nt][0] = 0u; acc[mt][nt][1] = 0u; }

    const uint32_t aOff = (uint32_t)(wm * 32 + (lane & 15)) * ROWB + (lane >> 4) * 16;
    const uint32_t bOff4 = (uint32_t)(wn * 32 + (lane & 7) + ((lane >> 4) & 1) * 8) * ROWB
                         + ((lane >> 3) & 1) * 16;

    const int crow = tid >> 2, cq = tid & 3;
    const float* aptr0 = Arow + (size_t)crow * K + cq * 16;
    const uint32_t cvtDstBase = smem + crow * ROWB + cq * 32;

    float ar[16];
    ldg16(ar, aptr0);
    load_b_tile(smem + HC_B_OFF, tid, Brow, K, 0);             cp_commit();
    load_b_tile(smem + HC_B_OFF + B_TILE, tid, Brow, K, BK);   cp_commit();
    load_b_tile(smem + HC_B_OFF + 2 * B_TILE, tid, Brow, K, 2 * BK); cp_commit();
    cvt_sts(ar, cvtDstBase, alpha);
    if (KT > 1) ldg16(ar, aptr0 + BK);
    cp_wait2();

    for (int t = 0; t < KT; t++) {
        __syncthreads();
        if (t + 1 < KT)
            cvt_sts(ar, cvtDstBase + (uint32_t)((t + 1) & 1) * A_TILE, alpha);
        if (t + 2 < KT)
            ldg16(ar, aptr0 + (size_t)(t + 2) * BK);
        if (t + 3 < KT)
            load_b_tile(smem + HC_B_OFF + (uint32_t)((t + 3) & 3) * B_TILE,
                        tid, Brow, K, (t + 3) * BK);
        cp_commit();
        mma_tile_h(acc, smem + (uint32_t)(t & 1) * A_TILE + aOff,
                   smem + HC_B_OFF + (uint32_t)(t & 3) * B_TILE + bOff4);
        cp_wait2();
    }
    cp_wait0();

    // epilogue: unpack half2 accs -> scale -> +bias -> (relu) -> half2 store
    const int rbase = m0 + wm * 32 + (lane >> 2);
    const int cbase = n0 + wn * 32 + 2 * (lane & 3);
    #pragma unroll
    for (int mt = 0; mt < 2; mt++) {
        #pragma unroll
        for (int nt = 0; nt < 4; nt++) {
            const int col = cbase + nt * 8;
            float b0 = bias[col], b1 = bias[col + 1];
            __half2 d0 = *(__half2*)&acc[mt][nt][0];   // (row, col), (row, col+1)
            __half2 d1 = *(__half2*)&acc[mt][nt][1];   // (row+8, col), (row+8, col+1)
            float v0 = __low2float(d0)  * scale + b0;
            float v1 = __high2float(d0) * scale + b1;
            float v2 = __low2float(d1)  * scale + b0;
            float v3 = __high2float(d1) * scale + b1;
            if (RELU) {
                v0 = fmaxf(v0, 0.0f); v1 = fmaxf(v1, 0.0f);
                v2 = fmaxf(v2, 0.0f); v3 = fmaxf(v3, 0.0f);
            }
            const int row = rbase + mt * 16;
            *(__half2*)(C + (size_t)row * ldc + col)       = __floats2half2_rn(v0, v1);
            *(__half2*)(C + (size_t)(row + 8) * ldc + col) = __floats2half2_rn(v2, v3);
        }
    }
}

// ---------------------------------------------------------------------------
// Batched fp32 -> fp16 transposed copy for the 5 weight matrices.
// ---------------------------------------------------------------------------
struct TJob { const float* in; __half* out; int R; int C; int tileStart; };
struct TJobs { TJob j[5]; int total; };

__global__ __launch_bounds__(256) void transpose_all(TJobs jobs)
{
    __shared__ float t[32][33];
    int b = blockIdx.x;
    int ji = 0;
    #pragma unroll
    for (int i = 1; i < 5; i++) if (b >= jobs.j[i].tileStart) ji = i;
    const TJob jb = jobs.j[ji];
    const int rel = b - jb.tileStart;
    const int tilesX = jb.C / 32;
    const int bx = (rel % tilesX) * 32;
    const int by = (rel / tilesX) * 32;
    const int tx = threadIdx.x, ty = threadIdx.y;
    #pragma unroll
    for (int i = 0; i < 32; i += 8)
        t[ty + i][tx] = jb.in[(size_t)(by + ty + i) * jb.C + bx + tx];
    __syncthreads();
    #pragma unroll
    for (int i = 0; i < 32; i += 8)
        jb.out[(size_t)(bx + ty + i) * jb.R + by + tx] = __float2half(t[tx][ty + i]);
}

// concat: cat[:, NHID:] = (half) target
__global__ void concat_h(const float* __restrict__ target, __half* __restrict__ cat)
{
    int idx = blockIdx.x * blockDim.x + threadIdx.x;
    if (idx >= NROWS * NFEAT / 2) return;
    int r = idx / (NFEAT / 2);
    int c2 = idx % (NFEAT / 2);
    float2 v = ((const float2*)target)[idx];
    *(__half2*)(cat + (size_t)r * NCAT + NHID + c2 * 2) = __floats2half2_rn(v.x, v.y);
}

// ---------------------------------------------------------------------------
// Row-wise log_softmax over NFEAT=512 columns, in place (fp32).
// ---------------------------------------------------------------------------
__global__ __launch_bounds__(256) void log_softmax_rows(float* __restrict__ io)
{
    const int row = blockIdx.x;
    float* x = io + (size_t)row * NFEAT;
    const int tid = threadIdx.x;
    __shared__ float red[8];

    float m = -INFINITY;
    for (int c = tid; c < NFEAT; c += 256) m = fmaxf(m, x[c]);
    #pragma unroll
    for (int o = 16; o; o >>= 1) m = fmaxf(m, __shfl_xor_sync(0xFFFFFFFFu, m, o));
    if ((tid & 31) == 0) red[tid >> 5] = m;
    __syncthreads();
    float rowmax = red[0];
    #pragma unroll
    for (int i = 1; i < 8; i++) rowmax = fmaxf(rowmax, red[i]);
    __syncthreads();

    float s = 0.0f;
    for (int c = tid; c < NFEAT; c += 256) s += expf(x[c] - rowmax);
    #pragma unroll
    for (int o = 16; o; o >>= 1) s += __shfl_xor_sync(0xFFFFFFFFu, s, o);
    if ((tid & 31) == 0) red[tid >> 5] = s;
    __syncthreads();
    float tot = 0.0f;
    #pragma unroll
    for (int i = 0; i < 8; i++) tot += red[i];
    const float lse = logf(tot) + rowmax;

    for (int c = tid; c < NFEAT; c += 256) x[c] = x[c] - lse;
}

// ---------------------------------------------------------------------------
// Launch
// ---------------------------------------------------------------------------
#define ADJ_SCALE 8192.0f
#define ADJ_INV   (1.0f / 8192.0f)

extern "C" void kernel_launch(void* const* d_in, const int* in_sizes, int n_in,
                              void* d_out, int out_size)
{
    const float* x      = (const float*)d_in[0];
    const float* target = (const float*)d_in[1];
    const float* adj0   = (const float*)d_in[2];
    const float* adj1   = (const float*)d_in[3];
    const float* gc1_w  = (const float*)d_in[4];
    const float* gc1_b  = (const float*)d_in[5];
    const float* gc2_w  = (const float*)d_in[6];
    const float* gc2_b  = (const float*)d_in[7];
    const float* lin1_w = (const float*)d_in[8];
    const float* lin1_b = (const float*)d_in[9];
    const float* lin2_w = (const float*)d_in[10];
    const float* lin2_b = (const float*)d_in[11];
    const float* lin3_w = (const float*)d_in[12];
    const float* lin3_b = (const float*)d_in[13];
    float* out = (float*)d_out;

    __half *xwT, *h1, *h1wT, *cat, *o4, *o5;
    __half *w1T, *w2T, *l1T, *l2T, *l3T;
    cudaGetSymbolAddress((void**)&xwT,  g_xwT);
    cudaGetSymbolAddress((void**)&h1,   g_h1);
    cudaGetSymbolAddress((void**)&h1wT, g_h1wT);
    cudaGetSymbolAddress((void**)&cat,  g_cat);
    cudaGetSymbolAddress((void**)&o4,   g_o4);
    cudaGetSymbolAddress((void**)&o5,   g_o5);
    cudaGetSymbolAddress((void**)&w1T,  g_w1T);
    cudaGetSymbolAddress((void**)&w2T,  g_w2T);
    cudaGetSymbolAddress((void**)&l1T,  g_l1T);
    cudaGetSymbolAddress((void**)&l2T,  g_l2T);
    cudaGetSymbolAddress((void**)&l3T,  g_l3T);

    cudaFuncSetAttribute(h_gemm<false, false, true, true>,   cudaFuncAttributeMaxDynamicSharedMemorySize, DYN_P);
    cudaFuncSetAttribute(h_gemm<true,  true,  true, false>,  cudaFuncAttributeMaxDynamicSharedMemorySize, DYN_P);
    cudaFuncSetAttribute(h_gemm<false, true,  false, false>, cudaFuncAttributeMaxDynamicSharedMemorySize, DYN_P);
    cudaFuncSetAttribute(hc_gemm<false, false, true, true>,  cudaFuncAttributeMaxDynamicSharedMemorySize, DYN_HC);
    cudaFuncSetAttribute(hc_gemm_hacc<true>,  cudaFuncAttributeMaxDynamicSharedMemorySize, DYN_HC);
    cudaFuncSetAttribute(hc_gemm_hacc<false>, cudaFuncAttributeMaxDynamicSharedMemorySize, DYN_HC);

    // Batched weight transposes ([K,N] -> [N,K] half), one launch.
    TJobs jobs;
    jobs.j[0] = { gc1_w,  w1T, NFEAT, NHID, 0 };
    jobs.j[1] = { gc2_w,  w2T, NHID,  NHID, 128 };
    jobs.j[2] = { lin1_w, l1T, NCAT,  NCAT, 192 };
    jobs.j[3] = { lin2_w, l2T, NCAT,  NCAT, 768 };
    jobs.j[4] = { lin3_w, l3T, NCAT,  NFEAT, 1344 };
    jobs.total = 1728;
    transpose_all<<<1728, dim3(32, 8)>>>(jobs);

    // 1. xwT = (x @ gc1_w)^T   (fp32 A, fp32 acc, transposed epilogue)
    hc_gemm<false, false, true, true><<<dim3(NHID / BN, NROWS / BM), 256, DYN_HC>>>(
        NFEAT, NROWS, x, w1T, nullptr, xwT, 1.0f, 1.0f);

    // 2. h1 = relu(adj0 @ xw + gc1_b)   (fp16 accumulators)
    hc_gemm_hacc<true><<<dim3(NHID / BN, NROWS / BM), 256, DYN_HC>>>(
        NROWS, NHID, adj0, xwT, gc1_b, h1, ADJ_SCALE, ADJ_INV);

    // 3. h1wT = (h1 @ gc2_w)^T  (pure fp16, fp32 acc, transposed epilogue)
    h_gemm<false, false, true, true><<<dim3(NHID / BN, NROWS / BM), 256, DYN_P>>>(
        NHID, NROWS, h1, w2T, nullptr, h1wT, 1.0f);

    // 4. cat[:, :256] = adj1 @ h1w + gc2_b   (fp16 accumulators, ldc = 768)
    hc_gemm_hacc<false><<<dim3(NHID / BN, NROWS / BM), 256, DYN_HC>>>(
        NROWS, NCAT, adj1, h1wT, gc2_b, cat, ADJ_SCALE, ADJ_INV);

    // 5. cat[:, 256:] = target_feats
    concat_h<<<(NROWS * NFEAT / 2 + 255) / 256, 256>>>(target, cat);

    // 6. o4 = relu(cat @ lin1_w + lin1_b)   (fp32 acc)
    h_gemm<true, true, true, false><<<dim3(NCAT / BN, NROWS / BM), 256, DYN_P>>>(
        NCAT, NCAT, cat, l1T, lin1_b, o4, 1.0f);

    // 7. o5 = relu(o4 @ lin2_w + lin2_b)
    h_gemm<true, true, true, false><<<dim3(NCAT / BN, NROWS / BM), 256, DYN_P>>>(
        NCAT, NCAT, o4, l2T, lin2_b, o5, 1.0f);

    // 8. out = o5 @ lin3_w + lin3_b   (fp32 out)
    h_gemm<false, true, false, false><<<dim3(NFEAT / BN, NROWS / BM), 256, DYN_P>>>(
        NCAT, NFEAT, o5, l3T, lin3_b, out, 1.0f);

    // 9. log_softmax in place
    log_softmax_rows<<<NROWS, 256>>>(out);
}

// round 15
// speedup vs baseline: 1.0039x; 1.0039x over previous
#include <cuda_runtime.h>
#include <cuda_fp16.h>
#include <math.h>
#include <stdint.h>

// Problem dims (fixed per reference)
#define NROWS 8192
#define NFEAT 512
#define NHID  256
#define NCAT  768   // NHID + NFEAT

// ---------------------------------------------------------------------------
// Scratch (static device globals)
// ---------------------------------------------------------------------------
__device__ __half g_xwT [NHID * NROWS];   // stores (x @ gc1_w)^T * 8192
__device__ __half g_h1  [NROWS * NHID];
__device__ __half g_h1wT[NHID * NROWS];   // stores (h1 @ gc2_w)^T * 8192
__device__ __half g_cat [NROWS * NCAT];
__device__ __half g_o4  [NROWS * NCAT];
__device__ __half g_o5  [NROWS * NCAT];
__device__ __half g_w1T [NHID * NFEAT];
__device__ __half g_w2T [NHID * NHID];
__device__ __half g_l1T [NCAT * NCAT];
__device__ __half g_l2T [NCAT * NCAT];
__device__ __half g_l3T [NFEAT * NCAT];

// ---------------------------------------------------------------------------
// Helpers (baseline PTX only)
// ---------------------------------------------------------------------------
__device__ __forceinline__ uint32_t smem_u32(const void* p) {
    uint32_t a;
    asm("{ .reg .u64 t; cvta.to.shared.u64 t, %1; cvt.u32.u64 %0, t; }"
        : "=r"(a) : "l"(p));
    return a;
}
__device__ __forceinline__ void cpasync16(uint32_t dst, const void* src) {
    asm volatile("cp.async.cg.shared.global [%0], [%1], 16;" :: "r"(dst), "l"(src));
}
__device__ __forceinline__ void cp_commit() {
    asm volatile("cp.async.commit_group;" ::: "memory");
}
__device__ __forceinline__ void cp_wait1() {
    asm volatile("cp.async.wait_group 1;" ::: "memory");
}
__device__ __forceinline__ void cp_wait2() {
    asm volatile("cp.async.wait_group 2;" ::: "memory");
}
__device__ __forceinline__ void cp_wait0() {
    asm volatile("cp.async.wait_group 0;" ::: "memory");
}
__device__ __forceinline__ void ldsm_x4(uint32_t* r, uint32_t addr) {
    asm volatile("ldmatrix.sync.aligned.m8n8.x4.shared.b16 {%0,%1,%2,%3}, [%4];"
                 : "=r"(r[0]), "=r"(r[1]), "=r"(r[2]), "=r"(r[3]) : "r"(addr));
}
__device__ __forceinline__ void mma_f16(float* c, const uint32_t* a, const uint32_t* b) {
    asm volatile(
        "mma.sync.aligned.m16n8k16.row.col.f32.f16.f16.f32 "
        "{%0,%1,%2,%3}, {%4,%5,%6,%7}, {%8,%9}, {%0,%1,%2,%3};"
        : "+f"(c[0]), "+f"(c[1]), "+f"(c[2]), "+f"(c[3])
        : "r"(a[0]), "r"(a[1]), "r"(a[2]), "r"(a[3]), "r"(b[0]), "r"(b[1]));
}
__device__ __forceinline__ uint32_t h2u(__half2 h) { return *(uint32_t*)&h; }

// ---------------------------------------------------------------------------
// Tiling: BM=64, BN=128, BK=64, 256 threads (8 warps 2x4), warp tile 32x32.
// fp16 tile row = 64 halfs (128B) + 16B pad = 144B -> conflict-free ldmatrix.
// ---------------------------------------------------------------------------
#define BM 64
#define BN 128
#define BK 64
#define ROWB 144
#define A_TILE (BM * ROWB)          // 9216
#define B_TILE (BN * ROWB)          // 18432
#define P_STAGE (A_TILE + B_TILE)   // 27648
#define DYN_P (3 * P_STAGE)         // 82944  -> occupancy 2
#define HC_B_OFF (2 * A_TILE)       // 18432
#define DYN_HC (HC_B_OFF + 4 * B_TILE)  // 92160 -> occupancy 2

// A half tile: 64 rows x 8 chunks = 512, 2/thread
__device__ __forceinline__ void load_a_tile(uint32_t base, int tid,
                                            const __half* rowp, int K, int k0) {
    #pragma unroll
    for (int i = 0; i < 2; i++) {
        const int c = tid + i * 256;
        const int row = c >> 3, q = c & 7;
        cpasync16(base + row * ROWB + q * 16, rowp + (size_t)row * K + k0 + q * 8);
    }
}
// B half tile: 128 rows x 8 chunks = 1024, 4/thread
__device__ __forceinline__ void load_b_tile(uint32_t base, int tid,
                                            const __half* rowp, int K, int k0) {
    #pragma unroll
    for (int i = 0; i < 4; i++) {
        const int c = tid + i * 256;
        const int row = c >> 3, q = c & 7;
        cpasync16(base + row * ROWB + q * 16, rowp + (size_t)row * K + k0 + q * 8);
    }
}

// fp32 A: 16 consecutive floats per thread (4x LDG.128)
__device__ __forceinline__ void ldg16(float* ar, const float* p) {
    float4 v0 = ((const float4*)p)[0];
    float4 v1 = ((const float4*)p)[1];
    float4 v2 = ((const float4*)p)[2];
    float4 v3 = ((const float4*)p)[3];
    ar[0]  = v0.x; ar[1]  = v0.y; ar[2]  = v0.z; ar[3]  = v0.w;
    ar[4]  = v1.x; ar[5]  = v1.y; ar[6]  = v1.z; ar[7]  = v1.w;
    ar[8]  = v2.x; ar[9]  = v2.y; ar[10] = v2.z; ar[11] = v2.w;
    ar[12] = v3.x; ar[13] = v3.y; ar[14] = v3.z; ar[15] = v3.w;
}
// convert 16 floats -> 16 halfs (NO scale: pure F2FP) -> 2x STS.128
__device__ __forceinline__ void cvt_sts(const float* ar, uint32_t dst) {
    uint32_t o[8];
    #pragma unroll
    for (int i = 0; i < 8; i++)
        o[i] = h2u(__floats2half2_rn(ar[2 * i], ar[2 * i + 1]));
    asm volatile("st.shared.v4.b32 [%0], {%1,%2,%3,%4};"
                 :: "r"(dst), "r"(o[0]), "r"(o[1]), "r"(o[2]), "r"(o[3]));
    asm volatile("st.shared.v4.b32 [%0], {%1,%2,%3,%4};"
                 :: "r"(dst + 16), "r"(o[4]), "r"(o[5]), "r"(o[6]), "r"(o[7]));
}

// ---- fragment load for one k-step ----
__device__ __forceinline__ void ld_frags(uint32_t aBase, uint32_t bBase4, int ks,
                                         uint32_t af[2][4], uint32_t bf[4][2]) {
    ldsm_x4(af[0], aBase + ks * 32);
    ldsm_x4(af[1], aBase + 16 * ROWB + ks * 32);
    uint32_t q[4];
    ldsm_x4(q, bBase4 + ks * 32);
    bf[0][0] = q[0]; bf[0][1] = q[1]; bf[1][0] = q[2]; bf[1][1] = q[3];
    ldsm_x4(q, bBase4 + 16 * ROWB + ks * 32);
    bf[2][0] = q[0]; bf[2][1] = q[1]; bf[3][0] = q[2]; bf[3][1] = q[3];
}

// ---- mainloop body: register-double-buffered ldsm/mma over one BK=64 tile ----
__device__ __forceinline__ void mma_tile(float acc[2][4][4],
                                         uint32_t aBase, uint32_t bBase4) {
    uint32_t af[2][2][4], bf[2][4][2];
    ld_frags(aBase, bBase4, 0, af[0], bf[0]);
    #pragma unroll
    for (int ks = 0; ks < 4; ks++) {
        const int cur = ks & 1;
        if (ks < 3)
            ld_frags(aBase, bBase4, ks + 1, af[cur ^ 1], bf[cur ^ 1]);
        #pragma unroll
        for (int mt = 0; mt < 2; mt++)
            #pragma unroll
            for (int nt = 0; nt < 4; nt++)
                mma_f16(acc[mt][nt], af[cur][mt], bf[cur][nt]);
    }
}

// ---- epilogue: normal (direct) or transposed (smem-staged) ----
template <bool RELU, bool BIAS, bool HALF_OUT, bool TRANS>
__device__ __forceinline__ void epilogue(float acc[2][4][4], float scale,
                                         const float* bias, void* C, int ldc,
                                         int m0, int n0, int wm, int wn,
                                         int lane, int wid, uint8_t* scratch) {
    if (!TRANS) {
        const int rbase = m0 + wm * 32 + (lane >> 2);
        const int cbase = n0 + wn * 32 + 2 * (lane & 3);
        #pragma unroll
        for (int mt = 0; mt < 2; mt++) {
            #pragma unroll
            for (int nt = 0; nt < 4; nt++) {
                const int col = cbase + nt * 8;
                float b0 = 0.0f, b1 = 0.0f;
                if (BIAS) { b0 = bias[col]; b1 = bias[col + 1]; }
                float v0 = acc[mt][nt][0] * scale + b0;
                float v1 = acc[mt][nt][1] * scale + b1;
                float v2 = acc[mt][nt][2] * scale + b0;
                float v3 = acc[mt][nt][3] * scale + b1;
                if (RELU) {
                    v0 = fmaxf(v0, 0.0f); v1 = fmaxf(v1, 0.0f);
                    v2 = fmaxf(v2, 0.0f); v3 = fmaxf(v3, 0.0f);
                }
                const int row = rbase + mt * 16;
                if (HALF_OUT) {
                    __half* Ch = (__half*)C;
                    *(__half2*)(Ch + (size_t)row * ldc + col)       = __floats2half2_rn(v0, v1);
                    *(__half2*)(Ch + (size_t)(row + 8) * ldc + col) = __floats2half2_rn(v2, v3);
                } else {
                    float* Cf = (float*)C;
                    *(float2*)(Cf + (size_t)row * ldc + col)       = make_float2(v0, v1);
                    *(float2*)(Cf + (size_t)(row + 8) * ldc + col) = make_float2(v2, v3);
                }
            }
        }
    } else {
        __half* sw = (__half*)scratch + (size_t)wid * (32 * 40);
        #pragma unroll
        for (int mt = 0; mt < 2; mt++) {
            #pragma unroll
            for (int nt = 0; nt < 4; nt++) {
                const int r = (lane >> 2) + mt * 16;
                const int c = 2 * (lane & 3) + nt * 8;
                sw[(size_t)c * 40 + r]           = __float2half(acc[mt][nt][0] * scale);
                sw[(size_t)(c + 1) * 40 + r]     = __float2half(acc[mt][nt][1] * scale);
                sw[(size_t)c * 40 + r + 8]       = __float2half(acc[mt][nt][2] * scale);
                sw[(size_t)(c + 1) * 40 + r + 8] = __float2half(acc[mt][nt][3] * scale);
            }
        }
        __syncwarp();
        __half* dst = (__half*)C + (size_t)(n0 + wn * 32 + lane) * ldc + m0 + wm * 32;
        const uint4* srow = (const uint4*)(sw + (size_t)lane * 40);
        uint4* d4 = (uint4*)dst;
        #pragma unroll
        for (int i = 0; i < 4; i++) d4[i] = srow[i];
    }
}

// ---------------------------------------------------------------------------
// Pure fp16 GEMM: C = A_h[M,K] @ Bt_h[N,K]^T * scale (+bias)(+relu)
// 3-stage pipeline, one __syncthreads per iteration.  K%64==0, KT>=2.
// ---------------------------------------------------------------------------
template <bool RELU, bool BIAS, bool HALF_OUT, bool TRANS>
__global__ __launch_bounds__(256, 2)
void h_gemm(int K, int ldc,
            const __half* __restrict__ A, const __half* __restrict__ Bt,
            const float* __restrict__ bias, void* __restrict__ C, float scale)
{
    extern __shared__ __align__(16) uint8_t dsraw[];
    const uint32_t smem = smem_u32(dsraw);
    const int tid = threadIdx.x, wid = tid >> 5, lane = tid & 31;
    const int wm = wid >> 2, wn = wid & 3;
    const int m0 = blockIdx.y * BM, n0 = blockIdx.x * BN;
    const int KT = K / BK;

    const __half* Arow = A + (size_t)m0 * K;
    const __half* Brow = Bt + (size_t)n0 * K;

    float acc[2][4][4];
    #pragma unroll
    for (int mt = 0; mt < 2; mt++)
        #pragma unroll
        for (int nt = 0; nt < 4; nt++)
            #pragma unroll
            for (int i = 0; i < 4; i++) acc[mt][nt][i] = 0.0f;

    const uint32_t aOff = (uint32_t)(wm * 32 + (lane & 15)) * ROWB + (lane >> 4) * 16;
    const uint32_t bOff4 = (uint32_t)(wn * 32 + (lane & 7) + ((lane >> 4) & 1) * 8) * ROWB
                         + ((lane >> 3) & 1) * 16;

    #pragma unroll
    for (int tt = 0; tt < 2; tt++) {
        const uint32_t st = smem + (uint32_t)tt * P_STAGE;
        load_a_tile(st, tid, Arow, K, tt * BK);
        load_b_tile(st + A_TILE, tid, Brow, K, tt * BK);
        cp_commit();
    }
    cp_wait1();

    int s = 0;
    for (int t = 0; t < KT; t++) {
        __syncthreads();
        if (t + 2 < KT) {
            const int sw = (s + 2 >= 3) ? s - 1 : s + 2;
            const uint32_t st = smem + (uint32_t)sw * P_STAGE;
            load_a_tile(st, tid, Arow, K, (t + 2) * BK);
            load_b_tile(st + A_TILE, tid, Brow, K, (t + 2) * BK);
        }
        cp_commit();
        const uint32_t st = smem + (uint32_t)s * P_STAGE;
        mma_tile(acc, st + aOff, st + A_TILE + bOff4);
        cp_wait1();
        s = (s + 1 == 3) ? 0 : s + 1;
    }
    cp_wait0();
    __syncthreads();
    epilogue<RELU, BIAS, HALF_OUT, TRANS>(acc, scale, bias, C, ldc,
                                          m0, n0, wm, wn, lane, wid, dsraw);
}

// ---------------------------------------------------------------------------
// fp32-A fused-convert GEMM: C = A_f32 @ Bt_h^T * scale (+bias)(+relu)
// A loaded LDG->regs one tile ahead, pure-F2FP converted into a 2-stage ring;
// B in 4-stage cp.async ring.  One __syncthreads per iteration.  KT>=3.
// ---------------------------------------------------------------------------
template <bool RELU, bool BIAS, bool HALF_OUT, bool TRANS>
__global__ __launch_bounds__(256, 2)
void hc_gemm(int K, int ldc,
             const float* __restrict__ A, const __half* __restrict__ Bt,
             const float* __restrict__ bias, void* __restrict__ C, float scale)
{
    extern __shared__ __align__(16) uint8_t dsraw[];
    const uint32_t smem = smem_u32(dsraw);
    const int tid = threadIdx.x, wid = tid >> 5, lane = tid & 31;
    const int wm = wid >> 2, wn = wid & 3;
    const int m0 = blockIdx.y * BM, n0 = blockIdx.x * BN;
    const int KT = K / BK;

    const float* Arow = A + (size_t)m0 * K;
    const __half* Brow = Bt + (size_t)n0 * K;

    float acc[2][4][4];
    #pragma unroll
    for (int mt = 0; mt < 2; mt++)
        #pragma unroll
        for (int nt = 0; nt < 4; nt++)
            #pragma unroll
            for (int i = 0; i < 4; i++) acc[mt][nt][i] = 0.0f;

    const uint32_t aOff = (uint32_t)(wm * 32 + (lane & 15)) * ROWB + (lane >> 4) * 16;
    const uint32_t bOff4 = (uint32_t)(wn * 32 + (lane & 7) + ((lane >> 4) & 1) * 8) * ROWB
                         + ((lane >> 3) & 1) * 16;

    // convert mapping: 64 rows x 64 floats; 4 threads/row, 16 floats each
    const int crow = tid >> 2, cq = tid & 3;
    const float* aptr0 = Arow + (size_t)crow * K + cq * 16;
    const uint32_t cvtDstBase = smem + crow * ROWB + cq * 32;

    float ar[16];
    // prologue
    ldg16(ar, aptr0);                                          // tile 0 -> regs
    load_b_tile(smem + HC_B_OFF, tid, Brow, K, 0);             cp_commit();
    load_b_tile(smem + HC_B_OFF + B_TILE, tid, Brow, K, BK);   cp_commit();
    load_b_tile(smem + HC_B_OFF + 2 * B_TILE, tid, Brow, K, 2 * BK); cp_commit();
    cvt_sts(ar, cvtDstBase);                                   // tile 0 -> A16[0]
    if (KT > 1) ldg16(ar, aptr0 + BK);                         // tile 1 -> regs
    cp_wait2();                                                // B0 landed (this thread)

    for (int t = 0; t < KT; t++) {
        __syncthreads();             // publish A16[t&1] + B tile t; free A16[(t+1)&1]
        if (t + 1 < KT)
            cvt_sts(ar, cvtDstBase + (uint32_t)((t + 1) & 1) * A_TILE);
        if (t + 2 < KT)
            ldg16(ar, aptr0 + (size_t)(t + 2) * BK);
        if (t + 3 < KT)
            load_b_tile(smem + HC_B_OFF + (uint32_t)((t + 3) & 3) * B_TILE,
                        tid, Brow, K, (t + 3) * BK);
        cp_commit();
        mma_tile(acc, smem + (uint32_t)(t & 1) * A_TILE + aOff,
                 smem + HC_B_OFF + (uint32_t)(t & 3) * B_TILE + bOff4);
        cp_wait2();                  // B tile t+1 landed (this thread)
    }
    cp_wait0();
    __syncthreads();
    epilogue<RELU, BIAS, HALF_OUT, TRANS>(acc, scale, bias, C, ldc,
                                          m0, n0, wm, wn, lane, wid, dsraw);
}

// ---------------------------------------------------------------------------
// Batched fp32 -> fp16 transposed copy for the 5 weight matrices.
// ---------------------------------------------------------------------------
struct TJob { const float* in; __half* out; int R; int C; int tileStart; };
struct TJobs { TJob j[5]; int total; };

__global__ __launch_bounds__(256) void transpose_all(TJobs jobs)
{
    __shared__ float t[32][33];
    int b = blockIdx.x;
    int ji = 0;
    #pragma unroll
    for (int i = 1; i < 5; i++) if (b >= jobs.j[i].tileStart) ji = i;
    const TJob jb = jobs.j[ji];
    const int rel = b - jb.tileStart;
    const int tilesX = jb.C / 32;
    const int bx = (rel % tilesX) * 32;
    const int by = (rel / tilesX) * 32;
    const int tx = threadIdx.x, ty = threadIdx.y;
    #pragma unroll
    for (int i = 0; i < 32; i += 8)
        t[ty + i][tx] = jb.in[(size_t)(by + ty + i) * jb.C + bx + tx];
    __syncthreads();
    #pragma unroll
    for (int i = 0; i < 32; i += 8)
        jb.out[(size_t)(bx + ty + i) * jb.R + by + tx] = __float2half(t[tx][ty + i]);
}

// concat: cat[:, NHID:] = (half) target
__global__ void concat_h(const float* __restrict__ target, __half* __restrict__ cat)
{
    int idx = blockIdx.x * blockDim.x + threadIdx.x;       // half2 units
    if (idx >= NROWS * NFEAT / 2) return;
    int r = idx / (NFEAT / 2);
    int c2 = idx % (NFEAT / 2);
    float2 v = ((const float2*)target)[idx];
    *(__half2*)(cat + (size_t)r * NCAT + NHID + c2 * 2) = __floats2half2_rn(v.x, v.y);
}

// ---------------------------------------------------------------------------
// Row-wise log_softmax over NFEAT=512 columns, in place (fp32).
// ---------------------------------------------------------------------------
__global__ __launch_bounds__(256) void log_softmax_rows(float* __restrict__ io)
{
    const int row = blockIdx.x;
    float* x = io + (size_t)row * NFEAT;
    const int tid = threadIdx.x;
    __shared__ float red[8];

    float m = -INFINITY;
    for (int c = tid; c < NFEAT; c += 256) m = fmaxf(m, x[c]);
    #pragma unroll
    for (int o = 16; o; o >>= 1) m = fmaxf(m, __shfl_xor_sync(0xFFFFFFFFu, m, o));
    if ((tid & 31) == 0) red[tid >> 5] = m;
    __syncthreads();
    float rowmax = red[0];
    #pragma unroll
    for (int i = 1; i < 8; i++) rowmax = fmaxf(rowmax, red[i]);
    __syncthreads();

    float s = 0.0f;
    for (int c = tid; c < NFEAT; c += 256) s += expf(x[c] - rowmax);
    #pragma unroll
    for (int o = 16; o; o >>= 1) s += __shfl_xor_sync(0xFFFFFFFFu, s, o);
    if ((tid & 31) == 0) red[tid >> 5] = s;
    __syncthreads();
    float tot = 0.0f;
    #pragma unroll
    for (int i = 0; i < 8; i++) tot += red[i];
    const float lse = logf(tot) + rowmax;

    for (int c = tid; c < NFEAT; c += 256) x[c] = x[c] - lse;
}

// ---------------------------------------------------------------------------
// Launch
// ---------------------------------------------------------------------------
#define ADJ_SCALE 8192.0f
#define ADJ_INV   (1.0f / 8192.0f)

extern "C" void kernel_launch(void* const* d_in, const int* in_sizes, int n_in,
                              void* d_out, int out_size)
{
    const float* x      = (const float*)d_in[0];
    const float* target = (const float*)d_in[1];
    const float* adj0   = (const float*)d_in[2];
    const float* adj1   = (const float*)d_in[3];
    const float* gc1_w  = (const float*)d_in[4];
    const float* gc1_b  = (const float*)d_in[5];
    const float* gc2_w  = (const float*)d_in[6];
    const float* gc2_b  = (const float*)d_in[7];
    const float* lin1_w = (const float*)d_in[8];
    const float* lin1_b = (const float*)d_in[9];
    const float* lin2_w = (const float*)d_in[10];
    const float* lin2_b = (const float*)d_in[11];
    const float* lin3_w = (const float*)d_in[12];
    const float* lin3_b = (const float*)d_in[13];
    float* out = (float*)d_out;

    __half *xwT, *h1, *h1wT, *cat, *o4, *o5;
    __half *w1T, *w2T, *l1T, *l2T, *l3T;
    cudaGetSymbolAddress((void**)&xwT,  g_xwT);
    cudaGetSymbolAddress((void**)&h1,   g_h1);
    cudaGetSymbolAddress((void**)&h1wT, g_h1wT);
    cudaGetSymbolAddress((void**)&cat,  g_cat);
    cudaGetSymbolAddress((void**)&o4,   g_o4);
    cudaGetSymbolAddress((void**)&o5,   g_o5);
    cudaGetSymbolAddress((void**)&w1T,  g_w1T);
    cudaGetSymbolAddress((void**)&w2T,  g_w2T);
    cudaGetSymbolAddress((void**)&l1T,  g_l1T);
    cudaGetSymbolAddress((void**)&l2T,  g_l2T);
    cudaGetSymbolAddress((void**)&l3T,  g_l3T);

    cudaFuncSetAttribute(h_gemm<false, false, true, true>,   cudaFuncAttributeMaxDynamicSharedMemorySize, DYN_P);
    cudaFuncSetAttribute(h_gemm<true,  true,  true, false>,  cudaFuncAttributeMaxDynamicSharedMemorySize, DYN_P);
    cudaFuncSetAttribute(h_gemm<false, true,  false, false>, cudaFuncAttributeMaxDynamicSharedMemorySize, DYN_P);
    cudaFuncSetAttribute(hc_gemm<false, false, true, true>,  cudaFuncAttributeMaxDynamicSharedMemorySize, DYN_HC);
    cudaFuncSetAttribute(hc_gemm<true,  true,  true, false>, cudaFuncAttributeMaxDynamicSharedMemorySize, DYN_HC);
    cudaFuncSetAttribute(hc_gemm<false, true,  true, false>, cudaFuncAttributeMaxDynamicSharedMemorySize, DYN_HC);

    // Batched weight transposes ([K,N] -> [N,K] half), one launch.
    TJobs jobs;
    jobs.j[0] = { gc1_w,  w1T, NFEAT, NHID, 0 };
    jobs.j[1] = { gc2_w,  w2T, NHID,  NHID, 128 };
    jobs.j[2] = { lin1_w, l1T, NCAT,  NCAT, 192 };
    jobs.j[3] = { lin2_w, l2T, NCAT,  NCAT, 768 };
    jobs.j[4] = { lin3_w, l3T, NCAT,  NFEAT, 1344 };
    jobs.total = 1728;
    transpose_all<<<1728, dim3(32, 8)>>>(jobs);

    // 1. xwT = (x @ gc1_w)^T * 8192   (fp32 A, pure-cvt, scale folded here)
    hc_gemm<false, false, true, true><<<dim3(NHID / BN, NROWS / BM), 256, DYN_HC>>>(
        NFEAT, NROWS, x, w1T, nullptr, xwT, ADJ_SCALE);

    // 2. h1 = relu(adj0 @ xw + gc1_b)   (adj converted unscaled; B carries 2^13)
    hc_gemm<true, true, true, false><<<dim3(NHID / BN, NROWS / BM), 256, DYN_HC>>>(
        NROWS, NHID, adj0, xwT, gc1_b, h1, ADJ_INV);

    // 3. h1wT = (h1 @ gc2_w)^T * 8192  (pure fp16, scale folded here)
    h_gemm<false, false, true, true><<<dim3(NHID / BN, NROWS / BM), 256, DYN_P>>>(
        NHID, NROWS, h1, w2T, nullptr, h1wT, ADJ_SCALE);

    // 4. cat[:, :256] = adj1 @ h1w + gc2_b   (ldc = 768)
    hc_gemm<false, true, true, false><<<dim3(NHID / BN, NROWS / BM), 256, DYN_HC>>>(
        NROWS, NCAT, adj1, h1wT, gc2_b, cat, ADJ_INV);

    // 5. cat[:, 256:] = target_feats
    concat_h<<<(NROWS * NFEAT / 2 + 255) / 256, 256>>>(target, cat);

    // 6. o4 = relu(cat @ lin1_w + lin1_b)
    h_gemm<true, true, true, false><<<dim3(NCAT / BN, NROWS / BM), 256, DYN_P>>>(
        NCAT, NCAT, cat, l1T, lin1_b, o4, 1.0f);

    // 7. o5 = relu(o4 @ lin2_w + lin2_b)
    h_gemm<true, true, true, false><<<dim3(NCAT / BN, NROWS / BM), 256, DYN_P>>>(
        NCAT, NCAT, o4, l2T, lin2_b, o5, 1.0f);

    // 8. out = o5 @ lin3_w + lin3_b   (fp32 out)
    h_gemm<false, true, false, false><<<dim3(NFEAT / BN, NROWS / BM), 256, DYN_P>>>(
        NCAT, NFEAT, o5, l3T, lin3_b, out, 1.0f);

    // 9. log_softmax in place
    log_softmax_rows<<<NROWS, 256>>>(out);
}